// round 4
// baseline (speedup 1.0000x reference)
#include <cuda_runtime.h>
#include <cstdint>
#include <math.h>

#define B_   2
#define S_   2048
#define D_   1024
#define H_   16
#define DK_  64
#define NROWS (B_ * S_)   // 4096
#define NWORDS (S_ / 64)  // 32 u64 mask words per row

// Scratch (allocation-free rule: __device__ globals)
__device__ float g_Q[NROWS * D_];
__device__ float g_K[NROWS * D_];
__device__ float g_V[NROWS * D_];
__device__ float g_A[NROWS * D_];
__device__ unsigned long long g_mbits[(size_t)B_ * S_ * NWORDS];  // 1 MB

// ---------------------------------------------------------------------------
// helpers
// ---------------------------------------------------------------------------
__device__ __forceinline__ uint32_t f2tf(float f) {
    uint32_t u;
    asm("cvt.rna.tf32.f32 %0, %1;" : "=r"(u) : "f"(f));
    return u;
}
__device__ __forceinline__ float tfbits(float f) {
    return __uint_as_float(f2tf(f));
}

__device__ __forceinline__ void mma_m16n8k8(float* c, const uint32_t* a,
                                            uint32_t b0, uint32_t b1) {
    asm volatile(
        "mma.sync.aligned.m16n8k8.row.col.f32.tf32.tf32.f32 "
        "{%0,%1,%2,%3}, {%4,%5,%6,%7}, {%8,%9}, {%0,%1,%2,%3};\n"
        : "+f"(c[0]), "+f"(c[1]), "+f"(c[2]), "+f"(c[3])
        : "r"(a[0]), "r"(a[1]), "r"(a[2]), "r"(a[3]), "r"(b0), "r"(b1));
}

__device__ __forceinline__ void cp16(void* sdst, const void* gsrc) {
    uint32_t s = (uint32_t)__cvta_generic_to_shared(sdst);
    asm volatile("cp.async.ca.shared.global [%0], [%1], 16;\n" :: "r"(s), "l"(gsrc));
}

// Named-barrier producer/consumer handshake. Barrier releases at 512 total
// arrivals: 256 from bar.arrive (non-blocking) + 256 from bar.sync (blocking).
__device__ __forceinline__ void barsync(int id) {
    asm volatile("bar.sync %0, 512;" :: "r"(id));
}
__device__ __forceinline__ void bararrive(int id) {
    asm volatile("bar.arrive %0, 512;" :: "r"(id));
}

// ---------------------------------------------------------------------------
// mask [B,1,S,S] int32 -> bit-packed u64 (bit j of word w = mask col 64w+j)
// one warp per output word; fully coalesced.
// ---------------------------------------------------------------------------
__global__ void __launch_bounds__(256) pack_mask(
    const int* __restrict__ mask, unsigned long long* __restrict__ bits)
{
    int gw = (int)((blockIdx.x * blockDim.x + threadIdx.x) >> 5);
    int lane = threadIdx.x & 31;
    const int* src = mask + (size_t)gw * 64;
    unsigned lo = __ballot_sync(0xffffffffu, src[lane] != 0);
    unsigned hi = __ballot_sync(0xffffffffu, src[lane + 32] != 0);
    bits[gw] = ((unsigned long long)hi << 32) | lo;
}

// ---------------------------------------------------------------------------
// C[M, Nd] = A[M, K] @ W[Nd, K]^T + bias  — tf32 mma, 3-stage cp.async
// Block 128x128, K-stage 32, 256 threads; warps 2(m) x 4(n), warp tile 64x32.
// ---------------------------------------------------------------------------
#define GP 36   // smem pitch: (36*r + c) % 32 == (4r + c) % 32 -> conflict-free frags
__global__ void __launch_bounds__(256, 2) gemm_tf32(
    const float* __restrict__ A, const float* __restrict__ W,
    const float* __restrict__ bias, float* __restrict__ C,
    int M, int Nd, int K)
{
    extern __shared__ float sm[];
    float* As = sm;                 // 3 * 128 * 36
    float* Bs = sm + 3 * 128 * GP;  // 3 * 128 * 36

    const int tid  = threadIdx.x;
    const int lane = tid & 31, wid = tid >> 5;
    const int g = lane >> 2, t = lane & 3;
    const int wm = (wid >> 2) * 64;
    const int wn = (wid & 3) * 32;
    const int m0 = blockIdx.y * 128, n0 = blockIdx.x * 128;

    const int k4 = (tid & 7) << 2;  // 0,4,...,28
    const int rb = tid >> 3;        // 0..31

    float acc[4][4][4];
    #pragma unroll
    for (int i = 0; i < 4; i++)
        #pragma unroll
        for (int j = 0; j < 4; j++)
            #pragma unroll
            for (int q = 0; q < 4; q++) acc[i][j][q] = 0.f;

    const int NS = K / 32;

    // prologue: stages 0, 1
    #pragma unroll
    for (int s = 0; s < 2; s++) {
        float* Ad = As + s * 128 * GP;
        float* Bd = Bs + s * 128 * GP;
        int kt = s * 32;
        #pragma unroll
        for (int j = 0; j < 4; j++) {
            int r = rb + 32 * j;
            cp16(Ad + r * GP + k4, A + (size_t)(m0 + r) * K + kt + k4);
            cp16(Bd + r * GP + k4, W + (size_t)(n0 + r) * K + kt + k4);
        }
        asm volatile("cp.async.commit_group;\n");
    }

    for (int s = 0; s < NS; s++) {
        if (s < NS - 1) asm volatile("cp.async.wait_group 1;\n");
        else            asm volatile("cp.async.wait_group 0;\n");
        __syncthreads();

        if (s + 2 < NS) {
            int kt = (s + 2) * 32;
            float* Ad = As + ((s + 2) % 3) * 128 * GP;
            float* Bd = Bs + ((s + 2) % 3) * 128 * GP;
            #pragma unroll
            for (int j = 0; j < 4; j++) {
                int r = rb + 32 * j;
                cp16(Ad + r * GP + k4, A + (size_t)(m0 + r) * K + kt + k4);
                cp16(Bd + r * GP + k4, W + (size_t)(n0 + r) * K + kt + k4);
            }
            asm volatile("cp.async.commit_group;\n");
        }

        const float* Ab = As + (s % 3) * 128 * GP;
        const float* Bb = Bs + (s % 3) * 128 * GP;

        #pragma unroll
        for (int ks = 0; ks < 4; ks++) {
            uint32_t af[4][4], bf[4][2];
            #pragma unroll
            for (int mt = 0; mt < 4; mt++) {
                int r = wm + mt * 16;
                af[mt][0] = f2tf(Ab[(r + g)     * GP + ks * 8 + t]);
                af[mt][1] = f2tf(Ab[(r + g + 8) * GP + ks * 8 + t]);
                af[mt][2] = f2tf(Ab[(r + g)     * GP + ks * 8 + t + 4]);
                af[mt][3] = f2tf(Ab[(r + g + 8) * GP + ks * 8 + t + 4]);
            }
            #pragma unroll
            for (int nt = 0; nt < 4; nt++) {
                int c = wn + nt * 8;
                bf[nt][0] = f2tf(Bb[(c + g) * GP + ks * 8 + t]);
                bf[nt][1] = f2tf(Bb[(c + g) * GP + ks * 8 + t + 4]);
            }
            #pragma unroll
            for (int mt = 0; mt < 4; mt++)
                #pragma unroll
                for (int nt = 0; nt < 4; nt++)
                    mma_m16n8k8(acc[mt][nt], af[mt], bf[nt][0], bf[nt][1]);
        }
    }

    // epilogue
    #pragma unroll
    for (int mt = 0; mt < 4; mt++) {
        int r0 = m0 + wm + mt * 16 + g;
        #pragma unroll
        for (int nt = 0; nt < 4; nt++) {
            int c = n0 + wn + nt * 8 + 2 * t;
            float2 bv = *(const float2*)(bias + c);
            float2 o0 = make_float2(acc[mt][nt][0] + bv.x, acc[mt][nt][1] + bv.y);
            float2 o1 = make_float2(acc[mt][nt][2] + bv.x, acc[mt][nt][3] + bv.y);
            *(float2*)(C + (size_t)r0 * Nd + c)       = o0;
            *(float2*)(C + (size_t)(r0 + 8) * Nd + c) = o1;
        }
    }
}

// ---------------------------------------------------------------------------
// Warp-specialized flash attention, tf32 mma.
// Block = 128 q-rows x one (b,h). 512 threads:
//   warps 0-7  : consumers, 16 q-rows each (softmax stats intra-warp)
//   warps 8-15 : producers, stage K/V (LDG -> RN tf32 cvt -> STS), 3-stage ring
// Handshake: named barriers FULL(s)=1+s, EMPTY(s)=4+s  (bar.arrive / bar.sync).
// Mask comes bit-packed from g_mbits (loaded pre-barrier, L2-hit hidden).
// ---------------------------------------------------------------------------
#define NST 3
__global__ void __launch_bounds__(512, 1) attn_tf32(
    const float* __restrict__ Qg, const float* __restrict__ Kg,
    const float* __restrict__ Vg, const unsigned long long* __restrict__ mbits,
    float* __restrict__ O)
{
    extern __shared__ float sm[];
    float* Qs = sm;                       // 128*68
    float* Ps = Qs + 128 * 68;            // 128*68
    float* Ks = Ps + 128 * 68;            // NST * 64*68
    float* Vs = Ks + NST * 64 * 68;       // NST * 64*72

    const int tid = threadIdx.x;
    const int bh = blockIdx.y, b = bh >> 4, h = bh & 15;
    const int q0 = blockIdx.x * 128;
    const int T = S_ / 64;                // 32 KV tiles

    // cooperative Q load [128 x 64], pre-converted to tf32 bits
    const float* Qb = Qg + ((size_t)(b * S_ + q0)) * D_ + h * DK_;
    for (int i = tid; i < 128 * 16; i += 512) {
        int r = i >> 4, c4 = (i & 15) << 2;
        float4 v = *(const float4*)(Qb + (size_t)r * D_ + c4);
        float* d = Qs + r * 68 + c4;
        d[0] = tfbits(v.x); d[1] = tfbits(v.y);
        d[2] = tfbits(v.z); d[3] = tfbits(v.w);
    }
    __syncthreads();

    if (tid >= 256) {
        // ----------------- producer -----------------
        const int p = tid - 256;
        for (int t = 0; t < T; t++) {
            int s = t % NST;
            if (t >= NST) barsync(4 + s);   // wait consumers done with stage s
            const float* Kb = Kg + ((size_t)(b * S_ + t * 64)) * D_ + h * DK_;
            const float* Vb = Vg + ((size_t)(b * S_ + t * 64)) * D_ + h * DK_;
            float* Kd = Ks + s * 64 * 68;
            float* Vd = Vs + s * 64 * 72;
            #pragma unroll
            for (int i = p; i < 64 * 16; i += 256) {
                int r = i >> 4, c4 = (i & 15) << 2;
                float4 kv = *(const float4*)(Kb + (size_t)r * D_ + c4);
                float* kd = Kd + r * 68 + c4;
                kd[0] = tfbits(kv.x); kd[1] = tfbits(kv.y);
                kd[2] = tfbits(kv.z); kd[3] = tfbits(kv.w);
                float4 vv = *(const float4*)(Vb + (size_t)r * D_ + c4);
                float* vd = Vd + r * 72 + c4;
                vd[0] = tfbits(vv.x); vd[1] = tfbits(vv.y);
                vd[2] = tfbits(vv.z); vd[3] = tfbits(vv.w);
            }
            bararrive(1 + s);               // stage s full
        }
        return;
    }

    // ----------------- consumer -----------------
    const int lane = tid & 31, wid = tid >> 5;
    const int g = lane >> 2, t4 = lane & 3;
    const int w16 = wid * 16;

    // Q fragments for this warp's 16 rows (already tf32 bits)
    uint32_t qf[8][4];
    #pragma unroll
    for (int ks = 0; ks < 8; ks++) {
        qf[ks][0] = __float_as_uint(Qs[(w16 + g)     * 68 + ks * 8 + t4]);
        qf[ks][1] = __float_as_uint(Qs[(w16 + g + 8) * 68 + ks * 8 + t4]);
        qf[ks][2] = __float_as_uint(Qs[(w16 + g)     * 68 + ks * 8 + t4 + 4]);
        qf[ks][3] = __float_as_uint(Qs[(w16 + g + 8) * 68 + ks * 8 + t4 + 4]);
    }

    float oacc[8][4];
    #pragma unroll
    for (int i = 0; i < 8; i++)
        #pragma unroll
        for (int j = 0; j < 4; j++) oacc[i][j] = 0.f;
    float mr0 = -INFINITY, mr1 = -INFINITY, lr0 = 0.f, lr1 = 0.f;

    const unsigned long long* mrow0 =
        mbits + (size_t)(b * S_ + q0 + w16 + g) * NWORDS;
    const unsigned long long* mrow1 =
        mbits + (size_t)(b * S_ + q0 + w16 + g + 8) * NWORDS;

    for (int t = 0; t < T; t++) {
        int s = t % NST;
        // issue mask-bit loads before the barrier (L2 latency hidden)
        unsigned long long mw0 = __ldg(mrow0 + t);
        unsigned long long mw1 = __ldg(mrow1 + t);

        barsync(1 + s);                     // wait stage s full
        const float* Kb = Ks + s * 64 * 68;
        const float* Vb = Vs + s * 64 * 72;

        // S = Q K^T
        float sacc[8][4];
        #pragma unroll
        for (int i = 0; i < 8; i++)
            #pragma unroll
            for (int j = 0; j < 4; j++) sacc[i][j] = 0.f;
        #pragma unroll
        for (int nt = 0; nt < 8; nt++) {
            #pragma unroll
            for (int ks = 0; ks < 8; ks++) {
                uint32_t b0 = __float_as_uint(Kb[(nt * 8 + g) * 68 + ks * 8 + t4]);
                uint32_t b1 = __float_as_uint(Kb[(nt * 8 + g) * 68 + ks * 8 + t4 + 4]);
                mma_m16n8k8(sacc[nt], qf[ks], b0, b1);
            }
        }

        // scale + mask (bit test) + row max
        const float scl = 0.125f;
        float rm0 = -INFINITY, rm1 = -INFINITY;
        #pragma unroll
        for (int nt = 0; nt < 8; nt++) {
            int sh = nt * 8 + 2 * t4;
            sacc[nt][0] = ((mw0 >> sh) & 1ull)       ? sacc[nt][0] * scl : -1e9f;
            sacc[nt][1] = ((mw0 >> (sh + 1)) & 1ull) ? sacc[nt][1] * scl : -1e9f;
            sacc[nt][2] = ((mw1 >> sh) & 1ull)       ? sacc[nt][2] * scl : -1e9f;
            sacc[nt][3] = ((mw1 >> (sh + 1)) & 1ull) ? sacc[nt][3] * scl : -1e9f;
            rm0 = fmaxf(rm0, fmaxf(sacc[nt][0], sacc[nt][1]));
            rm1 = fmaxf(rm1, fmaxf(sacc[nt][2], sacc[nt][3]));
        }
        rm0 = fmaxf(rm0, __shfl_xor_sync(0xffffffffu, rm0, 1));
        rm0 = fmaxf(rm0, __shfl_xor_sync(0xffffffffu, rm0, 2));
        rm1 = fmaxf(rm1, __shfl_xor_sync(0xffffffffu, rm1, 1));
        rm1 = fmaxf(rm1, __shfl_xor_sync(0xffffffffu, rm1, 2));

        float mn0 = fmaxf(mr0, rm0), mn1 = fmaxf(mr1, rm1);
        float a0 = __expf(mr0 - mn0), a1 = __expf(mr1 - mn1);
        float rs0 = 0.f, rs1 = 0.f;
        #pragma unroll
        for (int nt = 0; nt < 8; nt++) {
            float p0 = __expf(sacc[nt][0] - mn0);
            float p1 = __expf(sacc[nt][1] - mn0);
            float p2 = __expf(sacc[nt][2] - mn1);
            float p3 = __expf(sacc[nt][3] - mn1);
            rs0 += p0 + p1; rs1 += p2 + p3;
            int c = nt * 8 + 2 * t4;
            float2 lo = make_float2(tfbits(p0), tfbits(p1));
            float2 hi = make_float2(tfbits(p2), tfbits(p3));
            *(float2*)&Ps[(w16 + g)     * 68 + c] = lo;
            *(float2*)&Ps[(w16 + g + 8) * 68 + c] = hi;
        }
        rs0 += __shfl_xor_sync(0xffffffffu, rs0, 1);
        rs0 += __shfl_xor_sync(0xffffffffu, rs0, 2);
        rs1 += __shfl_xor_sync(0xffffffffu, rs1, 1);
        rs1 += __shfl_xor_sync(0xffffffffu, rs1, 2);
        lr0 = lr0 * a0 + rs0; lr1 = lr1 * a1 + rs1;
        mr0 = mn0; mr1 = mn1;
        #pragma unroll
        for (int nt = 0; nt < 8; nt++) {
            oacc[nt][0] *= a0; oacc[nt][1] *= a0;
            oacc[nt][2] *= a1; oacc[nt][3] *= a1;
        }
        __syncwarp();   // P stores visible to fragment loads across lanes

        // O += P @ V
        #pragma unroll
        for (int ks = 0; ks < 8; ks++) {
            uint32_t pa[4];
            pa[0] = __float_as_uint(Ps[(w16 + g)     * 68 + ks * 8 + t4]);
            pa[1] = __float_as_uint(Ps[(w16 + g + 8) * 68 + ks * 8 + t4]);
            pa[2] = __float_as_uint(Ps[(w16 + g)     * 68 + ks * 8 + t4 + 4]);
            pa[3] = __float_as_uint(Ps[(w16 + g + 8) * 68 + ks * 8 + t4 + 4]);
            #pragma unroll
            for (int nt = 0; nt < 8; nt++) {
                uint32_t b0 = __float_as_uint(Vb[(ks * 8 + t4)     * 72 + nt * 8 + g]);
                uint32_t b1 = __float_as_uint(Vb[(ks * 8 + t4 + 4) * 72 + nt * 8 + g]);
                mma_m16n8k8(oacc[nt], pa, b0, b1);
            }
        }
        bararrive(4 + s);                   // stage s empty
    }

    // write normalized output, heads re-merged
    float i0 = 1.f / lr0, i1 = 1.f / lr1;
    #pragma unroll
    for (int nt = 0; nt < 8; nt++) {
        int c = h * DK_ + nt * 8 + 2 * t4;
        size_t r0 = (size_t)(b * S_ + q0 + w16 + g) * D_ + c;
        size_t r1 = (size_t)(b * S_ + q0 + w16 + g + 8) * D_ + c;
        O[r0] = oacc[nt][0] * i0; O[r0 + 1] = oacc[nt][1] * i0;
        O[r1] = oacc[nt][2] * i1; O[r1 + 1] = oacc[nt][3] * i1;
    }
}

// ---------------------------------------------------------------------------
extern "C" void kernel_launch(void* const* d_in, const int* in_sizes, int n_in,
                              void* d_out, int out_size)
{
    const float* q    = (const float*)d_in[0];
    const float* k    = (const float*)d_in[1];
    const float* v    = (const float*)d_in[2];
    const int*   mask = (const int*)  d_in[3];
    const float* w_q  = (const float*)d_in[4];
    const float* b_q  = (const float*)d_in[5];
    const float* w_k  = (const float*)d_in[6];
    const float* b_k  = (const float*)d_in[7];
    const float* w_v  = (const float*)d_in[8];
    const float* b_v  = (const float*)d_in[9];
    const float* w_o  = (const float*)d_in[10];
    const float* b_o  = (const float*)d_in[11];
    float* out = (float*)d_out;

    float *Qp, *Kp, *Vp, *Ap;
    unsigned long long* Mp;
    cudaGetSymbolAddress((void**)&Qp, g_Q);
    cudaGetSymbolAddress((void**)&Kp, g_K);
    cudaGetSymbolAddress((void**)&Vp, g_V);
    cudaGetSymbolAddress((void**)&Ap, g_A);
    cudaGetSymbolAddress((void**)&Mp, g_mbits);

    const int gemm_smem = 3 * 2 * 128 * GP * sizeof(float);               // 110592
    const int attn_smem = (2 * 128 * 68 + NST * 64 * 68 + NST * 64 * 72) * sizeof(float); // 177152

    static bool attr_done = false;
    if (!attr_done) {
        cudaFuncSetAttribute(gemm_tf32,
            cudaFuncAttributeMaxDynamicSharedMemorySize, gemm_smem);
        cudaFuncSetAttribute(attn_tf32,
            cudaFuncAttributeMaxDynamicSharedMemorySize, attn_smem);
        attr_done = true;
    }

    // mask bit-pack: one warp per u64 word
    int nwords_total = B_ * S_ * NWORDS;           // 131072
    pack_mask<<<nwords_total / 8, 256>>>(mask, Mp);

    dim3 gemm_grid(D_ / 128, NROWS / 128);   // (8, 32)
    gemm_tf32<<<gemm_grid, 256, gemm_smem>>>(q, w_q, b_q, Qp, NROWS, D_, D_);
    gemm_tf32<<<gemm_grid, 256, gemm_smem>>>(k, w_k, b_k, Kp, NROWS, D_, D_);
    gemm_tf32<<<gemm_grid, 256, gemm_smem>>>(v, w_v, b_v, Vp, NROWS, D_, D_);

    attn_tf32<<<dim3(S_ / 128, B_ * H_), 512, attn_smem>>>(Qp, Kp, Vp, Mp, Ap);

    gemm_tf32<<<gemm_grid, 256, gemm_smem>>>(Ap, w_o, b_o, out, NROWS, D_, D_);
}

// round 5
// speedup vs baseline: 1.1779x; 1.1779x over previous
#include <cuda_runtime.h>
#include <cstdint>
#include <math.h>

#define B_   2
#define S_   2048
#define D_   1024
#define H_   16
#define DK_  64
#define NROWS (B_ * S_)   // 4096
#define NWORDS (S_ / 64)  // 32 u64 mask words per row

// Scratch (allocation-free rule: __device__ globals)
__device__ float g_Q[NROWS * D_];     // tf32 bits
__device__ float g_K[NROWS * D_];     // tf32 bits
__device__ float g_V[NROWS * D_];     // tf32 bits
__device__ float g_A[NROWS * D_];     // tf32 bits (attention out)
__device__ float g_qc[NROWS * D_];    // pre-converted activations
__device__ float g_kc[NROWS * D_];
__device__ float g_vc[NROWS * D_];
__device__ float g_wq[D_ * D_];       // pre-converted weights
__device__ float g_wk[D_ * D_];
__device__ float g_wv[D_ * D_];
__device__ float g_wo[D_ * D_];
__device__ unsigned long long g_mbits[(size_t)B_ * S_ * NWORDS];  // 1 MB

// ---------------------------------------------------------------------------
// helpers
// ---------------------------------------------------------------------------
__device__ __forceinline__ uint32_t f2tf(float f) {
    uint32_t u;
    asm("cvt.rna.tf32.f32 %0, %1;" : "=r"(u) : "f"(f));
    return u;
}
__device__ __forceinline__ float tfbits(float f) {
    return __uint_as_float(f2tf(f));
}

__device__ __forceinline__ void mma_m16n8k8(float* c, const uint32_t* a,
                                            uint32_t b0, uint32_t b1) {
    asm volatile(
        "mma.sync.aligned.m16n8k8.row.col.f32.tf32.tf32.f32 "
        "{%0,%1,%2,%3}, {%4,%5,%6,%7}, {%8,%9}, {%0,%1,%2,%3};\n"
        : "+f"(c[0]), "+f"(c[1]), "+f"(c[2]), "+f"(c[3])
        : "r"(a[0]), "r"(a[1]), "r"(a[2]), "r"(a[3]), "r"(b0), "r"(b1));
}

__device__ __forceinline__ void cp16(void* sdst, const void* gsrc) {
    uint32_t s = (uint32_t)__cvta_generic_to_shared(sdst);
    asm volatile("cp.async.ca.shared.global [%0], [%1], 16;\n" :: "r"(s), "l"(gsrc));
}
__device__ __forceinline__ uint32_t ldu(const float* p) {
    return __float_as_uint(*p);
}

// ---------------------------------------------------------------------------
// elementwise fp32 -> tf32-bits (RN) pre-pass
// ---------------------------------------------------------------------------
__global__ void __launch_bounds__(256) cvt_tf32(
    const float* __restrict__ src, float* __restrict__ dst, int n4)
{
    int i = blockIdx.x * blockDim.x + threadIdx.x;
    if (i >= n4) return;
    float4 v = ((const float4*)src)[i];
    v.x = tfbits(v.x); v.y = tfbits(v.y);
    v.z = tfbits(v.z); v.w = tfbits(v.w);
    ((float4*)dst)[i] = v;
}

// ---------------------------------------------------------------------------
// mask [B,1,S,S] int32 -> bit-packed u64
// ---------------------------------------------------------------------------
__global__ void __launch_bounds__(256) pack_mask(
    const int* __restrict__ mask, unsigned long long* __restrict__ bits)
{
    int gw = (int)((blockIdx.x * blockDim.x + threadIdx.x) >> 5);
    int lane = threadIdx.x & 31;
    const int* src = mask + (size_t)gw * 64;
    unsigned lo = __ballot_sync(0xffffffffu, src[lane] != 0);
    unsigned hi = __ballot_sync(0xffffffffu, src[lane + 32] != 0);
    bits[gw] = ((unsigned long long)hi << 32) | lo;
}

// ---------------------------------------------------------------------------
// C[M, Nd] = A[M, K] @ W[Nd, K]^T + bias — tf32 mma, 2-stage cp.async.
// A and W hold PRE-CONVERTED tf32 bits; mainloop has zero cvt.
// CVT: write tf32 bits (for downstream MMA consumers) vs plain fp32.
// ---------------------------------------------------------------------------
#define GP 36   // smem pitch: (36*r + c) % 32 == (4r + c) % 32 -> conflict-free frags
template <bool CVT>
__global__ void __launch_bounds__(256) gemm_tf32(
    const float* __restrict__ A, const float* __restrict__ W,
    const float* __restrict__ bias, float* __restrict__ C,
    int M, int Nd, int K)
{
    extern __shared__ float sm[];
    float* As = sm;                 // 2 * 128 * 36
    float* Bs = sm + 2 * 128 * GP;  // 2 * 128 * 36

    const int tid  = threadIdx.x;
    const int lane = tid & 31, wid = tid >> 5;
    const int g = lane >> 2, t = lane & 3;
    const int wm = (wid >> 2) * 64;
    const int wn = (wid & 3) * 32;
    const int m0 = blockIdx.y * 128, n0 = blockIdx.x * 128;

    const int k4 = (tid & 7) << 2;  // 0,4,...,28
    const int rb = tid >> 3;        // 0..31

    float acc[4][4][4];
    #pragma unroll
    for (int i = 0; i < 4; i++)
        #pragma unroll
        for (int j = 0; j < 4; j++)
            #pragma unroll
            for (int q = 0; q < 4; q++) acc[i][j][q] = 0.f;

    // prologue: stage 0
    {
        #pragma unroll
        for (int j = 0; j < 4; j++) {
            int r = rb + 32 * j;
            cp16(As + r * GP + k4, A + (size_t)(m0 + r) * K + k4);
            cp16(Bs + r * GP + k4, W + (size_t)(n0 + r) * K + k4);
        }
        asm volatile("cp.async.commit_group;\n");
    }

    const int NS = K / 32;
    for (int s = 0; s < NS; s++) {
        asm volatile("cp.async.wait_group 0;\n");
        __syncthreads();
        if (s + 1 < NS) {
            int kt = (s + 1) * 32;
            float* Ad = As + ((s + 1) & 1) * 128 * GP;
            float* Bd = Bs + ((s + 1) & 1) * 128 * GP;
            #pragma unroll
            for (int j = 0; j < 4; j++) {
                int r = rb + 32 * j;
                cp16(Ad + r * GP + k4, A + (size_t)(m0 + r) * K + kt + k4);
                cp16(Bd + r * GP + k4, W + (size_t)(n0 + r) * K + kt + k4);
            }
            asm volatile("cp.async.commit_group;\n");
        }
        const float* Ab = As + (s & 1) * 128 * GP;
        const float* Bb = Bs + (s & 1) * 128 * GP;

        #pragma unroll
        for (int ks = 0; ks < 4; ks++) {
            uint32_t af[4][4], bf[4][2];
            #pragma unroll
            for (int mt = 0; mt < 4; mt++) {
                int r = wm + mt * 16;
                af[mt][0] = ldu(&Ab[(r + g)     * GP + ks * 8 + t]);
                af[mt][1] = ldu(&Ab[(r + g + 8) * GP + ks * 8 + t]);
                af[mt][2] = ldu(&Ab[(r + g)     * GP + ks * 8 + t + 4]);
                af[mt][3] = ldu(&Ab[(r + g + 8) * GP + ks * 8 + t + 4]);
            }
            #pragma unroll
            for (int nt = 0; nt < 4; nt++) {
                int c = wn + nt * 8;
                bf[nt][0] = ldu(&Bb[(c + g) * GP + ks * 8 + t]);
                bf[nt][1] = ldu(&Bb[(c + g) * GP + ks * 8 + t + 4]);
            }
            #pragma unroll
            for (int mt = 0; mt < 4; mt++)
                #pragma unroll
                for (int nt = 0; nt < 4; nt++)
                    mma_m16n8k8(acc[mt][nt], af[mt], bf[nt][0], bf[nt][1]);
        }
    }

    // epilogue
    #pragma unroll
    for (int mt = 0; mt < 4; mt++) {
        int r0 = m0 + wm + mt * 16 + g;
        #pragma unroll
        for (int nt = 0; nt < 4; nt++) {
            int c = n0 + wn + nt * 8 + 2 * t;
            float2 bv = *(const float2*)(bias + c);
            float2 o0, o1;
            if (CVT) {
                o0 = make_float2(tfbits(acc[mt][nt][0] + bv.x), tfbits(acc[mt][nt][1] + bv.y));
                o1 = make_float2(tfbits(acc[mt][nt][2] + bv.x), tfbits(acc[mt][nt][3] + bv.y));
            } else {
                o0 = make_float2(acc[mt][nt][0] + bv.x, acc[mt][nt][1] + bv.y);
                o1 = make_float2(acc[mt][nt][2] + bv.x, acc[mt][nt][3] + bv.y);
            }
            *(float2*)(C + (size_t)r0 * Nd + c)       = o0;
            *(float2*)(C + (size_t)(r0 + 8) * Nd + c) = o1;
        }
    }
}

// ---------------------------------------------------------------------------
// Flash attention, tf32 mma, Br=256. 512 threads = 16 compute warps, each
// owning 16 q-rows (softmax stats intra-warp). K/V staged by self-issued
// cp.async into a 2-stage ring (inputs are pre-converted tf32 bits -> no cvt,
// no register round-trip). Mask bit-packed. One empty/real commit per iter
// keeps cp.async group accounting uniform.
// ---------------------------------------------------------------------------
__global__ void __launch_bounds__(512, 1) attn_tf32(
    const float* __restrict__ Qg, const float* __restrict__ Kg,
    const float* __restrict__ Vg, const unsigned long long* __restrict__ mbits,
    float* __restrict__ O)
{
    extern __shared__ float sm[];
    float* Qs = sm;                       // 256*68
    float* Ps = Qs + 256 * 68;            // 256*68
    float* Ks = Ps + 256 * 68;            // 2 * 64*68
    float* Vs = Ks + 2 * 64 * 68;         // 2 * 64*72

    const int tid = threadIdx.x;
    const int lane = tid & 31, wid = tid >> 5;
    const int g = lane >> 2, t4 = lane & 3;
    const int w16 = wid * 16;
    const int bh = blockIdx.y, b = bh >> 4, h = bh & 15;
    const int q0 = blockIdx.x * 256;
    const int T = S_ / 64;                // 32 KV tiles

    const float* Kg0 = Kg + ((size_t)(b * S_)) * D_ + h * DK_;
    const float* Vg0 = Vg + ((size_t)(b * S_)) * D_ + h * DK_;

    // prologue: stage KV tiles 0 and 1
    #pragma unroll
    for (int pt = 0; pt < 2; pt++) {
        const float* Kb = Kg0 + (size_t)(pt * 64) * D_;
        const float* Vb = Vg0 + (size_t)(pt * 64) * D_;
        float* Kd = Ks + pt * 64 * 68;
        float* Vd = Vs + pt * 64 * 72;
        #pragma unroll
        for (int i = tid; i < 64 * 16; i += 512) {
            int r = i >> 4, c4 = (i & 15) << 2;
            cp16(Kd + r * 68 + c4, Kb + (size_t)r * D_ + c4);
            cp16(Vd + r * 72 + c4, Vb + (size_t)r * D_ + c4);
        }
        asm volatile("cp.async.commit_group;\n");
    }

    // Q tile [256 x 64] (already tf32 bits) -> smem
    const float* Qb = Qg + ((size_t)(b * S_ + q0)) * D_ + h * DK_;
    for (int i = tid; i < 256 * 16; i += 512) {
        int r = i >> 4, c4 = (i & 15) << 2;
        *(float4*)(Qs + r * 68 + c4) = *(const float4*)(Qb + (size_t)r * D_ + c4);
    }
    __syncthreads();

    // Q fragments for this warp's 16 rows
    uint32_t qf[8][4];
    #pragma unroll
    for (int ks = 0; ks < 8; ks++) {
        qf[ks][0] = ldu(&Qs[(w16 + g)     * 68 + ks * 8 + t4]);
        qf[ks][1] = ldu(&Qs[(w16 + g + 8) * 68 + ks * 8 + t4]);
        qf[ks][2] = ldu(&Qs[(w16 + g)     * 68 + ks * 8 + t4 + 4]);
        qf[ks][3] = ldu(&Qs[(w16 + g + 8) * 68 + ks * 8 + t4 + 4]);
    }

    float oacc[8][4];
    #pragma unroll
    for (int i = 0; i < 8; i++)
        #pragma unroll
        for (int j = 0; j < 4; j++) oacc[i][j] = 0.f;
    float mr0 = -INFINITY, mr1 = -INFINITY, lr0 = 0.f, lr1 = 0.f;

    const unsigned long long* mrow0 =
        mbits + (size_t)(b * S_ + q0 + w16 + g) * NWORDS;
    const unsigned long long* mrow1 =
        mbits + (size_t)(b * S_ + q0 + w16 + g + 8) * NWORDS;

    for (int t = 0; t < T; t++) {
        int s = t & 1;
        unsigned long long mw0 = __ldg(mrow0 + t);
        unsigned long long mw1 = __ldg(mrow1 + t);

        asm volatile("cp.async.wait_group 1;\n");   // tile t landed
        __syncthreads();
        const float* Kb = Ks + s * 64 * 68;
        const float* Vb = Vs + s * 64 * 72;

        // S = Q K^T
        float sacc[8][4];
        #pragma unroll
        for (int i = 0; i < 8; i++)
            #pragma unroll
            for (int j = 0; j < 4; j++) sacc[i][j] = 0.f;
        #pragma unroll
        for (int nt = 0; nt < 8; nt++) {
            #pragma unroll
            for (int ks = 0; ks < 8; ks++) {
                uint32_t b0 = ldu(&Kb[(nt * 8 + g) * 68 + ks * 8 + t4]);
                uint32_t b1 = ldu(&Kb[(nt * 8 + g) * 68 + ks * 8 + t4 + 4]);
                mma_m16n8k8(sacc[nt], qf[ks], b0, b1);
            }
        }

        // scale + mask (bit test) + online softmax
        const float scl = 0.125f;
        float rm0 = -INFINITY, rm1 = -INFINITY;
        #pragma unroll
        for (int nt = 0; nt < 8; nt++) {
            int sh = nt * 8 + 2 * t4;
            sacc[nt][0] = ((mw0 >> sh) & 1ull)       ? sacc[nt][0] * scl : -1e9f;
            sacc[nt][1] = ((mw0 >> (sh + 1)) & 1ull) ? sacc[nt][1] * scl : -1e9f;
            sacc[nt][2] = ((mw1 >> sh) & 1ull)       ? sacc[nt][2] * scl : -1e9f;
            sacc[nt][3] = ((mw1 >> (sh + 1)) & 1ull) ? sacc[nt][3] * scl : -1e9f;
            rm0 = fmaxf(rm0, fmaxf(sacc[nt][0], sacc[nt][1]));
            rm1 = fmaxf(rm1, fmaxf(sacc[nt][2], sacc[nt][3]));
        }
        rm0 = fmaxf(rm0, __shfl_xor_sync(0xffffffffu, rm0, 1));
        rm0 = fmaxf(rm0, __shfl_xor_sync(0xffffffffu, rm0, 2));
        rm1 = fmaxf(rm1, __shfl_xor_sync(0xffffffffu, rm1, 1));
        rm1 = fmaxf(rm1, __shfl_xor_sync(0xffffffffu, rm1, 2));

        float mn0 = fmaxf(mr0, rm0), mn1 = fmaxf(mr1, rm1);
        float a0 = __expf(mr0 - mn0), a1 = __expf(mr1 - mn1);
        float rs0 = 0.f, rs1 = 0.f;
        #pragma unroll
        for (int nt = 0; nt < 8; nt++) {
            float p0 = __expf(sacc[nt][0] - mn0);
            float p1 = __expf(sacc[nt][1] - mn0);
            float p2 = __expf(sacc[nt][2] - mn1);
            float p3 = __expf(sacc[nt][3] - mn1);
            rs0 += p0 + p1; rs1 += p2 + p3;
            int c = nt * 8 + 2 * t4;
            float2 lo = make_float2(tfbits(p0), tfbits(p1));
            float2 hi = make_float2(tfbits(p2), tfbits(p3));
            *(float2*)&Ps[(w16 + g)     * 68 + c] = lo;
            *(float2*)&Ps[(w16 + g + 8) * 68 + c] = hi;
        }
        rs0 += __shfl_xor_sync(0xffffffffu, rs0, 1);
        rs0 += __shfl_xor_sync(0xffffffffu, rs0, 2);
        rs1 += __shfl_xor_sync(0xffffffffu, rs1, 1);
        rs1 += __shfl_xor_sync(0xffffffffu, rs1, 2);
        lr0 = lr0 * a0 + rs0; lr1 = lr1 * a1 + rs1;
        mr0 = mn0; mr1 = mn1;
        #pragma unroll
        for (int nt = 0; nt < 8; nt++) {
            oacc[nt][0] *= a0; oacc[nt][1] *= a0;
            oacc[nt][2] *= a1; oacc[nt][3] *= a1;
        }
        __syncwarp();   // P stores visible across lanes of this warp

        // O += P @ V
        #pragma unroll
        for (int ks = 0; ks < 8; ks++) {
            uint32_t pa[4];
            pa[0] = ldu(&Ps[(w16 + g)     * 68 + ks * 8 + t4]);
            pa[1] = ldu(&Ps[(w16 + g + 8) * 68 + ks * 8 + t4]);
            pa[2] = ldu(&Ps[(w16 + g)     * 68 + ks * 8 + t4 + 4]);
            pa[3] = ldu(&Ps[(w16 + g + 8) * 68 + ks * 8 + t4 + 4]);
            #pragma unroll
            for (int nt = 0; nt < 8; nt++) {
                uint32_t b0 = ldu(&Vb[(ks * 8 + t4)     * 72 + nt * 8 + g]);
                uint32_t b1 = ldu(&Vb[(ks * 8 + t4 + 4) * 72 + nt * 8 + g]);
                mma_m16n8k8(oacc[nt], pa, b0, b1);
            }
        }

        __syncthreads();              // all warps done reading stage s
        if (t + 2 < T) {              // refill stage s with tile t+2
            const float* Kb2 = Kg0 + (size_t)((t + 2) * 64) * D_;
            const float* Vb2 = Vg0 + (size_t)((t + 2) * 64) * D_;
            float* Kd = Ks + s * 64 * 68;
            float* Vd = Vs + s * 64 * 72;
            #pragma unroll
            for (int i = tid; i < 64 * 16; i += 512) {
                int r = i >> 4, c4 = (i & 15) << 2;
                cp16(Kd + r * 68 + c4, Kb2 + (size_t)r * D_ + c4);
                cp16(Vd + r * 72 + c4, Vb2 + (size_t)r * D_ + c4);
            }
        }
        asm volatile("cp.async.commit_group;\n");   // real or empty: keeps accounting uniform
    }

    // write normalized output as tf32 bits (consumed by final GEMM)
    float i0 = 1.f / lr0, i1 = 1.f / lr1;
    #pragma unroll
    for (int nt = 0; nt < 8; nt++) {
        int c = h * DK_ + nt * 8 + 2 * t4;
        size_t r0 = (size_t)(b * S_ + q0 + w16 + g) * D_ + c;
        size_t r1 = (size_t)(b * S_ + q0 + w16 + g + 8) * D_ + c;
        O[r0] = tfbits(oacc[nt][0] * i0); O[r0 + 1] = tfbits(oacc[nt][1] * i0);
        O[r1] = tfbits(oacc[nt][2] * i1); O[r1 + 1] = tfbits(oacc[nt][3] * i1);
    }
}

// ---------------------------------------------------------------------------
extern "C" void kernel_launch(void* const* d_in, const int* in_sizes, int n_in,
                              void* d_out, int out_size)
{
    const float* q    = (const float*)d_in[0];
    const float* k    = (const float*)d_in[1];
    const float* v    = (const float*)d_in[2];
    const int*   mask = (const int*)  d_in[3];
    const float* w_q  = (const float*)d_in[4];
    const float* b_q  = (const float*)d_in[5];
    const float* w_k  = (const float*)d_in[6];
    const float* b_k  = (const float*)d_in[7];
    const float* w_v  = (const float*)d_in[8];
    const float* b_v  = (const float*)d_in[9];
    const float* w_o  = (const float*)d_in[10];
    const float* b_o  = (const float*)d_in[11];
    float* out = (float*)d_out;

    float *Qp, *Kp, *Vp, *Ap, *qc, *kc, *vc, *wq, *wk, *wv, *wo;
    unsigned long long* Mp;
    cudaGetSymbolAddress((void**)&Qp, g_Q);
    cudaGetSymbolAddress((void**)&Kp, g_K);
    cudaGetSymbolAddress((void**)&Vp, g_V);
    cudaGetSymbolAddress((void**)&Ap, g_A);
    cudaGetSymbolAddress((void**)&qc, g_qc);
    cudaGetSymbolAddress((void**)&kc, g_kc);
    cudaGetSymbolAddress((void**)&vc, g_vc);
    cudaGetSymbolAddress((void**)&wq, g_wq);
    cudaGetSymbolAddress((void**)&wk, g_wk);
    cudaGetSymbolAddress((void**)&wv, g_wv);
    cudaGetSymbolAddress((void**)&wo, g_wo);
    cudaGetSymbolAddress((void**)&Mp, g_mbits);

    const int gemm_smem = 2 * 2 * 128 * GP * sizeof(float);   // 73728
    const int attn_smem = (2 * 256 * 68 + 2 * 64 * 68 + 2 * 64 * 72) * sizeof(float); // 210944

    static bool attr_done = false;
    if (!attr_done) {
        cudaFuncSetAttribute(gemm_tf32<true>,
            cudaFuncAttributeMaxDynamicSharedMemorySize, gemm_smem);
        cudaFuncSetAttribute(gemm_tf32<false>,
            cudaFuncAttributeMaxDynamicSharedMemorySize, gemm_smem);
        cudaFuncSetAttribute(attn_tf32,
            cudaFuncAttributeMaxDynamicSharedMemorySize, attn_smem);
        attr_done = true;
    }

    // pre-passes: mask bit-pack + tf32 conversion of activations/weights
    pack_mask<<<(B_ * S_ * NWORDS) / 8, 256>>>(mask, Mp);
    const int nact4 = NROWS * D_ / 4;   // 1,048,576
    const int nw4   = D_ * D_ / 4;      //   262,144
    cvt_tf32<<<nact4 / 256, 256>>>(q, qc, nact4);
    cvt_tf32<<<nact4 / 256, 256>>>(k, kc, nact4);
    cvt_tf32<<<nact4 / 256, 256>>>(v, vc, nact4);
    cvt_tf32<<<nw4 / 256, 256>>>(w_q, wq, nw4);
    cvt_tf32<<<nw4 / 256, 256>>>(w_k, wk, nw4);
    cvt_tf32<<<nw4 / 256, 256>>>(w_v, wv, nw4);
    cvt_tf32<<<nw4 / 256, 256>>>(w_o, wo, nw4);

    dim3 gemm_grid(D_ / 128, NROWS / 128);   // (8, 32)
    gemm_tf32<true><<<gemm_grid, 256, gemm_smem>>>(qc, wq, b_q, Qp, NROWS, D_, D_);
    gemm_tf32<true><<<gemm_grid, 256, gemm_smem>>>(kc, wk, b_k, Kp, NROWS, D_, D_);
    gemm_tf32<true><<<gemm_grid, 256, gemm_smem>>>(vc, wv, b_v, Vp, NROWS, D_, D_);

    attn_tf32<<<dim3(S_ / 256, B_ * H_), 512, attn_smem>>>(Qp, Kp, Vp, Mp, Ap);

    gemm_tf32<false><<<gemm_grid, 256, gemm_smem>>>(Ap, wo, b_o, out, NROWS, D_, D_);
}

// round 6
// speedup vs baseline: 1.1836x; 1.0048x over previous
#include <cuda_runtime.h>
#include <cstdint>
#include <math.h>

#define B_   2
#define S_   2048
#define D_   1024
#define H_   16
#define DK_  64
#define NROWS (B_ * S_)   // 4096
#define NWORDS (S_ / 64)  // 32 u64 mask words per row

// Scratch (allocation-free rule: __device__ globals)
__device__ float g_Q[NROWS * D_];     // tf32 bits (pre-scaled by 0.125)
__device__ float g_K[NROWS * D_];     // tf32 bits
__device__ float g_V[NROWS * D_];     // tf32 bits
__device__ float g_A[NROWS * D_];     // tf32 bits (attention out)
__device__ float g_qc[NROWS * D_];    // pre-converted activations
__device__ float g_kc[NROWS * D_];
__device__ float g_vc[NROWS * D_];
__device__ float g_wq[D_ * D_];       // pre-converted weights
__device__ float g_wk[D_ * D_];
__device__ float g_wv[D_ * D_];
__device__ float g_wo[D_ * D_];
__device__ unsigned long long g_mbits[(size_t)B_ * S_ * NWORDS];  // 1 MB

// ---------------------------------------------------------------------------
// helpers
// ---------------------------------------------------------------------------
__device__ __forceinline__ uint32_t f2tf(float f) {
    uint32_t u;
    asm("cvt.rna.tf32.f32 %0, %1;" : "=r"(u) : "f"(f));
    return u;
}
__device__ __forceinline__ float tfbits(float f) {
    return __uint_as_float(f2tf(f));
}

__device__ __forceinline__ void mma_m16n8k8(float* c, const uint32_t* a,
                                            uint32_t b0, uint32_t b1) {
    asm volatile(
        "mma.sync.aligned.m16n8k8.row.col.f32.tf32.tf32.f32 "
        "{%0,%1,%2,%3}, {%4,%5,%6,%7}, {%8,%9}, {%0,%1,%2,%3};\n"
        : "+f"(c[0]), "+f"(c[1]), "+f"(c[2]), "+f"(c[3])
        : "r"(a[0]), "r"(a[1]), "r"(a[2]), "r"(a[3]), "r"(b0), "r"(b1));
}

__device__ __forceinline__ void cp16(void* sdst, const void* gsrc) {
    uint32_t s = (uint32_t)__cvta_generic_to_shared(sdst);
    asm volatile("cp.async.ca.shared.global [%0], [%1], 16;\n" :: "r"(s), "l"(gsrc));
}
__device__ __forceinline__ uint32_t ldu(const float* p) {
    return __float_as_uint(*p);
}

// ---------------------------------------------------------------------------
// elementwise fp32 -> tf32-bits (RN) pre-pass
// ---------------------------------------------------------------------------
__global__ void __launch_bounds__(256) cvt_tf32(
    const float* __restrict__ src, float* __restrict__ dst, int n4)
{
    int i = blockIdx.x * blockDim.x + threadIdx.x;
    if (i >= n4) return;
    float4 v = ((const float4*)src)[i];
    v.x = tfbits(v.x); v.y = tfbits(v.y);
    v.z = tfbits(v.z); v.w = tfbits(v.w);
    ((float4*)dst)[i] = v;
}

// ---------------------------------------------------------------------------
// mask [B,1,S,S] int32 -> bit-packed u64
// ---------------------------------------------------------------------------
__global__ void __launch_bounds__(256) pack_mask(
    const int* __restrict__ mask, unsigned long long* __restrict__ bits)
{
    int gw = (int)((blockIdx.x * blockDim.x + threadIdx.x) >> 5);
    int lane = threadIdx.x & 31;
    const int* src = mask + (size_t)gw * 64;
    unsigned lo = __ballot_sync(0xffffffffu, src[lane] != 0);
    unsigned hi = __ballot_sync(0xffffffffu, src[lane + 32] != 0);
    bits[gw] = ((unsigned long long)hi << 32) | lo;
}

// ---------------------------------------------------------------------------
// C[M, Nd] = A[M, K] @ W[Nd, K]^T + bias — tf32 mma, 2-stage cp.async.
// Block 128(m) x 256(n), BK=32, 256 threads; warps 2(m) x 4(n), warp tile
// 64x64 -> 1.0 LDS per MMA. Inputs are PRE-CONVERTED tf32 bits (no cvt in
// the mainloop).
// MODE: 0 = plain fp32 out, 1 = tf32-bits out, 2 = tf32-bits out scaled by
// 0.125 (exact power-of-2; used for Q so attention needs no score scaling).
// ---------------------------------------------------------------------------
#define GP 36   // smem pitch: (36*r + c) % 32 == (4r + c) % 32 -> conflict-free frags
template <int MODE>
__global__ void __launch_bounds__(256) gemm_tf32(
    const float* __restrict__ A, const float* __restrict__ W,
    const float* __restrict__ bias, float* __restrict__ C,
    int M, int Nd, int K)
{
    extern __shared__ float sm[];
    float* As = sm;                 // 2 * 128 * 36
    float* Bs = sm + 2 * 128 * GP;  // 2 * 256 * 36

    const int tid  = threadIdx.x;
    const int lane = tid & 31, wid = tid >> 5;
    const int g = lane >> 2, t = lane & 3;
    const int wm = (wid >> 2) * 64;   // 0 or 64
    const int wn = (wid & 3) * 64;    // 0,64,128,192
    const int m0 = blockIdx.y * 128, n0 = blockIdx.x * 256;

    const int k4 = (tid & 7) << 2;  // 0,4,...,28
    const int rb = tid >> 3;        // 0..31

    float acc[4][8][4];
    #pragma unroll
    for (int i = 0; i < 4; i++)
        #pragma unroll
        for (int j = 0; j < 8; j++)
            #pragma unroll
            for (int q = 0; q < 4; q++) acc[i][j][q] = 0.f;

    // prologue: stage 0
    {
        #pragma unroll
        for (int j = 0; j < 4; j++) {
            int r = rb + 32 * j;
            cp16(As + r * GP + k4, A + (size_t)(m0 + r) * K + k4);
        }
        #pragma unroll
        for (int j = 0; j < 8; j++) {
            int r = rb + 32 * j;
            cp16(Bs + r * GP + k4, W + (size_t)(n0 + r) * K + k4);
        }
        asm volatile("cp.async.commit_group;\n");
    }

    const int NS = K / 32;
    for (int s = 0; s < NS; s++) {
        asm volatile("cp.async.wait_group 0;\n");
        __syncthreads();
        if (s + 1 < NS) {
            int kt = (s + 1) * 32;
            float* Ad = As + ((s + 1) & 1) * 128 * GP;
            float* Bd = Bs + ((s + 1) & 1) * 256 * GP;
            #pragma unroll
            for (int j = 0; j < 4; j++) {
                int r = rb + 32 * j;
                cp16(Ad + r * GP + k4, A + (size_t)(m0 + r) * K + kt + k4);
            }
            #pragma unroll
            for (int j = 0; j < 8; j++) {
                int r = rb + 32 * j;
                cp16(Bd + r * GP + k4, W + (size_t)(n0 + r) * K + kt + k4);
            }
            asm volatile("cp.async.commit_group;\n");
        }
        const float* Ab = As + (s & 1) * 128 * GP;
        const float* Bb = Bs + (s & 1) * 256 * GP;

        #pragma unroll
        for (int ks = 0; ks < 4; ks++) {
            uint32_t af[4][4], bf[8][2];
            #pragma unroll
            for (int mt = 0; mt < 4; mt++) {
                int r = wm + mt * 16;
                af[mt][0] = ldu(&Ab[(r + g)     * GP + ks * 8 + t]);
                af[mt][1] = ldu(&Ab[(r + g + 8) * GP + ks * 8 + t]);
                af[mt][2] = ldu(&Ab[(r + g)     * GP + ks * 8 + t + 4]);
                af[mt][3] = ldu(&Ab[(r + g + 8) * GP + ks * 8 + t + 4]);
            }
            #pragma unroll
            for (int nt = 0; nt < 8; nt++) {
                int c = wn + nt * 8;
                bf[nt][0] = ldu(&Bb[(c + g) * GP + ks * 8 + t]);
                bf[nt][1] = ldu(&Bb[(c + g) * GP + ks * 8 + t + 4]);
            }
            #pragma unroll
            for (int mt = 0; mt < 4; mt++)
                #pragma unroll
                for (int nt = 0; nt < 8; nt++)
                    mma_m16n8k8(acc[mt][nt], af[mt], bf[nt][0], bf[nt][1]);
        }
    }

    // epilogue
    #pragma unroll
    for (int mt = 0; mt < 4; mt++) {
        int r0 = m0 + wm + mt * 16 + g;
        #pragma unroll
        for (int nt = 0; nt < 8; nt++) {
            int c = n0 + wn + nt * 8 + 2 * t;
            float2 bv = *(const float2*)(bias + c);
            float2 o0, o1;
            if (MODE == 0) {
                o0 = make_float2(acc[mt][nt][0] + bv.x, acc[mt][nt][1] + bv.y);
                o1 = make_float2(acc[mt][nt][2] + bv.x, acc[mt][nt][3] + bv.y);
            } else if (MODE == 1) {
                o0 = make_float2(tfbits(acc[mt][nt][0] + bv.x), tfbits(acc[mt][nt][1] + bv.y));
                o1 = make_float2(tfbits(acc[mt][nt][2] + bv.x), tfbits(acc[mt][nt][3] + bv.y));
            } else {
                o0 = make_float2(tfbits(0.125f * (acc[mt][nt][0] + bv.x)),
                                 tfbits(0.125f * (acc[mt][nt][1] + bv.y)));
                o1 = make_float2(tfbits(0.125f * (acc[mt][nt][2] + bv.x)),
                                 tfbits(0.125f * (acc[mt][nt][3] + bv.y)));
            }
            *(float2*)(C + (size_t)r0 * Nd + c)       = o0;
            *(float2*)(C + (size_t)(r0 + 8) * Nd + c) = o1;
        }
    }
}

// ---------------------------------------------------------------------------
// Flash attention, tf32 mma, Br=256. 512 threads = 16 compute warps, each
// owning 16 q-rows. K/V staged by cp.async 2-stage ring (pre-converted tf32
// bits). Q arrives pre-scaled by 0.125 -> no score scaling here. Mask is
// bit-packed.
// ---------------------------------------------------------------------------
__global__ void __launch_bounds__(512, 1) attn_tf32(
    const float* __restrict__ Qg, const float* __restrict__ Kg,
    const float* __restrict__ Vg, const unsigned long long* __restrict__ mbits,
    float* __restrict__ O)
{
    extern __shared__ float sm[];
    float* Qs = sm;                       // 256*68
    float* Ps = Qs + 256 * 68;            // 256*68
    float* Ks = Ps + 256 * 68;            // 2 * 64*68
    float* Vs = Ks + 2 * 64 * 68;         // 2 * 64*72

    const int tid = threadIdx.x;
    const int lane = tid & 31, wid = tid >> 5;
    const int g = lane >> 2, t4 = lane & 3;
    const int w16 = wid * 16;
    const int bh = blockIdx.y, b = bh >> 4, h = bh & 15;
    const int q0 = blockIdx.x * 256;
    const int T = S_ / 64;                // 32 KV tiles

    const float* Kg0 = Kg + ((size_t)(b * S_)) * D_ + h * DK_;
    const float* Vg0 = Vg + ((size_t)(b * S_)) * D_ + h * DK_;

    // prologue: stage KV tiles 0 and 1
    #pragma unroll
    for (int pt = 0; pt < 2; pt++) {
        const float* Kb = Kg0 + (size_t)(pt * 64) * D_;
        const float* Vb = Vg0 + (size_t)(pt * 64) * D_;
        float* Kd = Ks + pt * 64 * 68;
        float* Vd = Vs + pt * 64 * 72;
        #pragma unroll
        for (int i = tid; i < 64 * 16; i += 512) {
            int r = i >> 4, c4 = (i & 15) << 2;
            cp16(Kd + r * 68 + c4, Kb + (size_t)r * D_ + c4);
            cp16(Vd + r * 72 + c4, Vb + (size_t)r * D_ + c4);
        }
        asm volatile("cp.async.commit_group;\n");
    }

    // Q tile [256 x 64] (already tf32 bits, pre-scaled) -> smem
    const float* Qb = Qg + ((size_t)(b * S_ + q0)) * D_ + h * DK_;
    for (int i = tid; i < 256 * 16; i += 512) {
        int r = i >> 4, c4 = (i & 15) << 2;
        *(float4*)(Qs + r * 68 + c4) = *(const float4*)(Qb + (size_t)r * D_ + c4);
    }
    __syncthreads();

    // Q fragments for this warp's 16 rows
    uint32_t qf[8][4];
    #pragma unroll
    for (int ks = 0; ks < 8; ks++) {
        qf[ks][0] = ldu(&Qs[(w16 + g)     * 68 + ks * 8 + t4]);
        qf[ks][1] = ldu(&Qs[(w16 + g + 8) * 68 + ks * 8 + t4]);
        qf[ks][2] = ldu(&Qs[(w16 + g)     * 68 + ks * 8 + t4 + 4]);
        qf[ks][3] = ldu(&Qs[(w16 + g + 8) * 68 + ks * 8 + t4 + 4]);
    }

    float oacc[8][4];
    #pragma unroll
    for (int i = 0; i < 8; i++)
        #pragma unroll
        for (int j = 0; j < 4; j++) oacc[i][j] = 0.f;
    float mr0 = -INFINITY, mr1 = -INFINITY, lr0 = 0.f, lr1 = 0.f;

    const unsigned long long* mrow0 =
        mbits + (size_t)(b * S_ + q0 + w16 + g) * NWORDS;
    const unsigned long long* mrow1 =
        mbits + (size_t)(b * S_ + q0 + w16 + g + 8) * NWORDS;

    for (int t = 0; t < T; t++) {
        int s = t & 1;
        unsigned long long mw0 = __ldg(mrow0 + t);
        unsigned long long mw1 = __ldg(mrow1 + t);

        asm volatile("cp.async.wait_group 1;\n");   // tile t landed
        __syncthreads();
        const float* Kb = Ks + s * 64 * 68;
        const float* Vb = Vs + s * 64 * 72;

        // S = Q K^T (Q pre-scaled)
        float sacc[8][4];
        #pragma unroll
        for (int i = 0; i < 8; i++)
            #pragma unroll
            for (int j = 0; j < 4; j++) sacc[i][j] = 0.f;
        #pragma unroll
        for (int nt = 0; nt < 8; nt++) {
            #pragma unroll
            for (int ks = 0; ks < 8; ks++) {
                uint32_t b0 = ldu(&Kb[(nt * 8 + g) * 68 + ks * 8 + t4]);
                uint32_t b1 = ldu(&Kb[(nt * 8 + g) * 68 + ks * 8 + t4 + 4]);
                mma_m16n8k8(sacc[nt], qf[ks], b0, b1);
            }
        }

        // mask (bit test) + online softmax
        float rm0 = -INFINITY, rm1 = -INFINITY;
        #pragma unroll
        for (int nt = 0; nt < 8; nt++) {
            int sh = nt * 8 + 2 * t4;
            sacc[nt][0] = ((mw0 >> sh) & 1ull)       ? sacc[nt][0] : -1e9f;
            sacc[nt][1] = ((mw0 >> (sh + 1)) & 1ull) ? sacc[nt][1] : -1e9f;
            sacc[nt][2] = ((mw1 >> sh) & 1ull)       ? sacc[nt][2] : -1e9f;
            sacc[nt][3] = ((mw1 >> (sh + 1)) & 1ull) ? sacc[nt][3] : -1e9f;
            rm0 = fmaxf(rm0, fmaxf(sacc[nt][0], sacc[nt][1]));
            rm1 = fmaxf(rm1, fmaxf(sacc[nt][2], sacc[nt][3]));
        }
        rm0 = fmaxf(rm0, __shfl_xor_sync(0xffffffffu, rm0, 1));
        rm0 = fmaxf(rm0, __shfl_xor_sync(0xffffffffu, rm0, 2));
        rm1 = fmaxf(rm1, __shfl_xor_sync(0xffffffffu, rm1, 1));
        rm1 = fmaxf(rm1, __shfl_xor_sync(0xffffffffu, rm1, 2));

        float mn0 = fmaxf(mr0, rm0), mn1 = fmaxf(mr1, rm1);
        float a0 = __expf(mr0 - mn0), a1 = __expf(mr1 - mn1);
        float rs0 = 0.f, rs1 = 0.f;
        #pragma unroll
        for (int nt = 0; nt < 8; nt++) {
            float p0 = __expf(sacc[nt][0] - mn0);
            float p1 = __expf(sacc[nt][1] - mn0);
            float p2 = __expf(sacc[nt][2] - mn1);
            float p3 = __expf(sacc[nt][3] - mn1);
            rs0 += p0 + p1; rs1 += p2 + p3;
            int c = nt * 8 + 2 * t4;
            float2 lo = make_float2(tfbits(p0), tfbits(p1));
            float2 hi = make_float2(tfbits(p2), tfbits(p3));
            *(float2*)&Ps[(w16 + g)     * 68 + c] = lo;
            *(float2*)&Ps[(w16 + g + 8) * 68 + c] = hi;
        }
        rs0 += __shfl_xor_sync(0xffffffffu, rs0, 1);
        rs0 += __shfl_xor_sync(0xffffffffu, rs0, 2);
        rs1 += __shfl_xor_sync(0xffffffffu, rs1, 1);
        rs1 += __shfl_xor_sync(0xffffffffu, rs1, 2);
        lr0 = lr0 * a0 + rs0; lr1 = lr1 * a1 + rs1;
        mr0 = mn0; mr1 = mn1;
        #pragma unroll
        for (int nt = 0; nt < 8; nt++) {
            oacc[nt][0] *= a0; oacc[nt][1] *= a0;
            oacc[nt][2] *= a1; oacc[nt][3] *= a1;
        }
        __syncwarp();   // P stores visible across lanes of this warp

        // O += P @ V
        #pragma unroll
        for (int ks = 0; ks < 8; ks++) {
            uint32_t pa[4];
            pa[0] = ldu(&Ps[(w16 + g)     * 68 + ks * 8 + t4]);
            pa[1] = ldu(&Ps[(w16 + g + 8) * 68 + ks * 8 + t4]);
            pa[2] = ldu(&Ps[(w16 + g)     * 68 + ks * 8 + t4 + 4]);
            pa[3] = ldu(&Ps[(w16 + g + 8) * 68 + ks * 8 + t4 + 4]);
            #pragma unroll
            for (int nt = 0; nt < 8; nt++) {
                uint32_t b0 = ldu(&Vb[(ks * 8 + t4)     * 72 + nt * 8 + g]);
                uint32_t b1 = ldu(&Vb[(ks * 8 + t4 + 4) * 72 + nt * 8 + g]);
                mma_m16n8k8(oacc[nt], pa, b0, b1);
            }
        }

        __syncthreads();              // all warps done reading stage s
        if (t + 2 < T) {              // refill stage s with tile t+2
            const float* Kb2 = Kg0 + (size_t)((t + 2) * 64) * D_;
            const float* Vb2 = Vg0 + (size_t)((t + 2) * 64) * D_;
            float* Kd = Ks + s * 64 * 68;
            float* Vd = Vs + s * 64 * 72;
            #pragma unroll
            for (int i = tid; i < 64 * 16; i += 512) {
                int r = i >> 4, c4 = (i & 15) << 2;
                cp16(Kd + r * 68 + c4, Kb2 + (size_t)r * D_ + c4);
                cp16(Vd + r * 72 + c4, Vb2 + (size_t)r * D_ + c4);
            }
        }
        asm volatile("cp.async.commit_group;\n");   // real or empty: uniform accounting
    }

    // write normalized output as tf32 bits (consumed by final GEMM)
    float i0 = 1.f / lr0, i1 = 1.f / lr1;
    #pragma unroll
    for (int nt = 0; nt < 8; nt++) {
        int c = h * DK_ + nt * 8 + 2 * t4;
        size_t r0 = (size_t)(b * S_ + q0 + w16 + g) * D_ + c;
        size_t r1 = (size_t)(b * S_ + q0 + w16 + g + 8) * D_ + c;
        O[r0] = tfbits(oacc[nt][0] * i0); O[r0 + 1] = tfbits(oacc[nt][1] * i0);
        O[r1] = tfbits(oacc[nt][2] * i1); O[r1 + 1] = tfbits(oacc[nt][3] * i1);
    }
}

// ---------------------------------------------------------------------------
extern "C" void kernel_launch(void* const* d_in, const int* in_sizes, int n_in,
                              void* d_out, int out_size)
{
    const float* q    = (const float*)d_in[0];
    const float* k    = (const float*)d_in[1];
    const float* v    = (const float*)d_in[2];
    const int*   mask = (const int*)  d_in[3];
    const float* w_q  = (const float*)d_in[4];
    const float* b_q  = (const float*)d_in[5];
    const float* w_k  = (const float*)d_in[6];
    const float* b_k  = (const float*)d_in[7];
    const float* w_v  = (const float*)d_in[8];
    const float* b_v  = (const float*)d_in[9];
    const float* w_o  = (const float*)d_in[10];
    const float* b_o  = (const float*)d_in[11];
    float* out = (float*)d_out;

    float *Qp, *Kp, *Vp, *Ap, *qc, *kc, *vc, *wq, *wk, *wv, *wo;
    unsigned long long* Mp;
    cudaGetSymbolAddress((void**)&Qp, g_Q);
    cudaGetSymbolAddress((void**)&Kp, g_K);
    cudaGetSymbolAddress((void**)&Vp, g_V);
    cudaGetSymbolAddress((void**)&Ap, g_A);
    cudaGetSymbolAddress((void**)&qc, g_qc);
    cudaGetSymbolAddress((void**)&kc, g_kc);
    cudaGetSymbolAddress((void**)&vc, g_vc);
    cudaGetSymbolAddress((void**)&wq, g_wq);
    cudaGetSymbolAddress((void**)&wk, g_wk);
    cudaGetSymbolAddress((void**)&wv, g_wv);
    cudaGetSymbolAddress((void**)&wo, g_wo);
    cudaGetSymbolAddress((void**)&Mp, g_mbits);

    const int gemm_smem = 2 * (128 + 256) * GP * sizeof(float);   // 110592
    const int attn_smem = (2 * 256 * 68 + 2 * 64 * 68 + 2 * 64 * 72) * sizeof(float); // 210944

    static bool attr_done = false;
    if (!attr_done) {
        cudaFuncSetAttribute(gemm_tf32<0>,
            cudaFuncAttributeMaxDynamicSharedMemorySize, gemm_smem);
        cudaFuncSetAttribute(gemm_tf32<1>,
            cudaFuncAttributeMaxDynamicSharedMemorySize, gemm_smem);
        cudaFuncSetAttribute(gemm_tf32<2>,
            cudaFuncAttributeMaxDynamicSharedMemorySize, gemm_smem);
        cudaFuncSetAttribute(attn_tf32,
            cudaFuncAttributeMaxDynamicSharedMemorySize, attn_smem);
        attr_done = true;
    }

    // pre-passes: mask bit-pack + tf32 conversion of activations/weights
    pack_mask<<<(B_ * S_ * NWORDS) / 8, 256>>>(mask, Mp);
    const int nact4 = NROWS * D_ / 4;   // 1,048,576
    const int nw4   = D_ * D_ / 4;      //   262,144
    cvt_tf32<<<nact4 / 256, 256>>>(q, qc, nact4);
    cvt_tf32<<<nact4 / 256, 256>>>(k, kc, nact4);
    cvt_tf32<<<nact4 / 256, 256>>>(v, vc, nact4);
    cvt_tf32<<<nw4 / 256, 256>>>(w_q, wq, nw4);
    cvt_tf32<<<nw4 / 256, 256>>>(w_k, wk, nw4);
    cvt_tf32<<<nw4 / 256, 256>>>(w_v, wv, nw4);
    cvt_tf32<<<nw4 / 256, 256>>>(w_o, wo, nw4);

    dim3 gemm_grid(D_ / 256, NROWS / 128);   // (4, 32) = 128 blocks
    gemm_tf32<2><<<gemm_grid, 256, gemm_smem>>>(qc, wq, b_q, Qp, NROWS, D_, D_);
    gemm_tf32<1><<<gemm_grid, 256, gemm_smem>>>(kc, wk, b_k, Kp, NROWS, D_, D_);
    gemm_tf32<1><<<gemm_grid, 256, gemm_smem>>>(vc, wv, b_v, Vp, NROWS, D_, D_);

    attn_tf32<<<dim3(S_ / 256, B_ * H_), 512, attn_smem>>>(Qp, Kp, Vp, Mp, Ap);

    gemm_tf32<0><<<gemm_grid, 256, gemm_smem>>>(Ap, wo, b_o, out, NROWS, D_, D_);
}